// round 2
// baseline (speedup 1.0000x reference)
#include <cuda_runtime.h>

#define MAXN 100000
#define MAXE 1600000
#define NEG 0.2f

// ---------------- scratch (static device globals; no allocation) -------------
__device__ float    g_h0 [MAXN * 16];   // relu(x@W0)
__device__ float    g_hl [MAXN * 96];   // source transform (current layer)
__device__ float    g_hr [MAXN * 96];   // target transform (current layer)
__device__ float    g_acc[MAXN * 96];   // layer-1 accumulator = skip + b1 + msgs (pre-relu h1)
__device__ float    g_p  [MAXE * 3];    // per-edge scores -> exp(p)
__device__ unsigned g_m  [MAXN * 3];    // per-node per-head max (order-encoded)
__device__ float    g_den[MAXN * 3];    // per-node per-head softmax denominator
__device__ int      g_src[MAXE];
__device__ int      g_dst[MAXE];
__device__ int      g_is64;             // edge_index dtype flag (1 = int64)

// order-preserving float<->uint encoding for atomicMax on floats
__device__ __forceinline__ unsigned fenc(float f) {
    unsigned u = __float_as_uint(f);
    return (u & 0x80000000u) ? ~u : (u | 0x80000000u);
}
__device__ __forceinline__ float fdec(unsigned u) {
    return __uint_as_float((u & 0x80000000u) ? (u & 0x7fffffffu) : ~u);
}

// ---------------- kernels ----------------------------------------------------

// Detect whether edge_index is int64 or int32. Node ids < 2^17, so for int64
// every odd 32-bit word is 0. For int32 data (uniform ids in [0,1e5)), the
// chance all 32 sampled odd words are 0 is (1e-5)^32 ~ 0.
__global__ void k_detect(const int* __restrict__ p) {
    int acc = 0;
#pragma unroll
    for (int i = 1; i < 64; i += 2) acc |= p[i];
    g_is64 = (acc == 0) ? 1 : 0;
}

__global__ void k_edges(const void* __restrict__ ei, int E) {
    int i = blockIdx.x * blockDim.x + threadIdx.x;
    if (i >= E) return;
    if (g_is64) {
        const long long* p = (const long long*)ei;
        g_src[i] = (int)p[i];
        g_dst[i] = (int)p[E + i];
    } else {
        const int* p = (const int*)ei;
        g_src[i] = p[i];
        g_dst[i] = p[E + i];
    }
}

__global__ void k_reset(int n3) {
    int i = blockIdx.x * blockDim.x + threadIdx.x;
    if (i < n3) { g_m[i] = 0u; g_den[i] = 0.f; }
}

// h0 = relu(x @ W0)  : [n,128]@[128,16]
__global__ void k_lin0(const float* __restrict__ x, const float* __restrict__ W0, int n) {
    int t = blockIdx.x * blockDim.x + threadIdx.x;
    if (t >= n * 16) return;
    int row = t >> 4, c = t & 15;
    const float* xr = x + row * 128;
    float acc = 0.f;
#pragma unroll 8
    for (int k = 0; k < 128; k++) acc = fmaf(xr[k], W0[k * 16 + c], acc);
    g_h0[t] = fmaxf(acc, 0.f);
}

// layer-1 node transforms: hl = h0@Wl+bl, hr = h0@Wr+br, acc = h0@Wf+bf+b1
// block = (96,4), 16 rows per block, all weights staged in shared
__global__ void k_node1(const float* __restrict__ Wl, const float* __restrict__ bl,
                        const float* __restrict__ Wr, const float* __restrict__ br,
                        const float* __restrict__ Wf, const float* __restrict__ bf,
                        const float* __restrict__ b1, int n) {
    __shared__ float sW[3 * 16 * 96];
    __shared__ float sh[16 * 16];
    int c = threadIdx.x, ty = threadIdx.y;
    int tid = ty * 96 + c;
    int row0 = blockIdx.x * 16;
    for (int i = tid; i < 1536; i += 384) {
        sW[i] = Wl[i]; sW[1536 + i] = Wr[i]; sW[3072 + i] = Wf[i];
    }
    for (int i = tid; i < 256; i += 384) {
        int r = i >> 4, k = i & 15;
        int row = row0 + r;
        sh[i] = (row < n) ? g_h0[row * 16 + k] : 0.f;
    }
    __syncthreads();
    for (int rl = ty; rl < 16; rl += 4) {
        int row = row0 + rl;
        if (row >= n) continue;
        float a0 = bl[c], a1 = br[c], a2 = bf[c] + b1[c];
#pragma unroll
        for (int k = 0; k < 16; k++) {
            float hk = sh[rl * 16 + k];
            a0 = fmaf(hk, sW[k * 96 + c], a0);
            a1 = fmaf(hk, sW[1536 + k * 96 + c], a1);
            a2 = fmaf(hk, sW[3072 + k * 96 + c], a2);
        }
        g_hl[row * 96 + c] = a0;
        g_hr[row * 96 + c] = a1;
        g_acc[row * 96 + c] = a2;
    }
}

// layer-2 node transforms from pre-relu accumulator (relu applied on load):
// hl = h1@Wl2+bl2, hr = h1@Wr2+br2, out = h1@Wlast+blast+b2
// block = (96,4), 16 rows per block, K=96 in 6 k-tiles of 16
__global__ void k_node2(const float* __restrict__ Wl, const float* __restrict__ bl,
                        const float* __restrict__ Wr, const float* __restrict__ br,
                        const float* __restrict__ Wo, const float* __restrict__ bo,
                        const float* __restrict__ b2, float* __restrict__ out, int n) {
    __shared__ float sW[3 * 16 * 96];
    __shared__ float sh[16 * 16];
    int c = threadIdx.x, ty = threadIdx.y;
    int tid = ty * 96 + c;
    int row0 = blockIdx.x * 16;
    float a0[4], a1[4], a2[4];
#pragma unroll
    for (int j = 0; j < 4; j++) { a0[j] = bl[c]; a1[j] = br[c]; a2[j] = bo[c] + b2[c]; }
    for (int kt = 0; kt < 6; kt++) {
        __syncthreads();
        for (int i = tid; i < 1536; i += 384) {
            sW[i] = Wl[kt * 1536 + i];
            sW[1536 + i] = Wr[kt * 1536 + i];
            sW[3072 + i] = Wo[kt * 1536 + i];
        }
        for (int i = tid; i < 256; i += 384) {
            int r = i >> 4, k = i & 15;
            int row = row0 + r;
            float v = (row < n) ? g_acc[row * 96 + kt * 16 + k] : 0.f;
            sh[i] = fmaxf(v, 0.f);   // relu(h1)
        }
        __syncthreads();
#pragma unroll
        for (int j = 0; j < 4; j++) {
            int rl = ty + 4 * j;
#pragma unroll
            for (int k = 0; k < 16; k++) {
                float hk = sh[rl * 16 + k];
                a0[j] = fmaf(hk, sW[k * 96 + c], a0[j]);
                a1[j] = fmaf(hk, sW[1536 + k * 96 + c], a1[j]);
                a2[j] = fmaf(hk, sW[3072 + k * 96 + c], a2[j]);
            }
        }
    }
#pragma unroll
    for (int j = 0; j < 4; j++) {
        int row = row0 + ty + 4 * j;
        if (row < n) {
            g_hl[row * 96 + c] = a0[j];
            g_hr[row * 96 + c] = a1[j];
            out[row * 96 + c] = a2[j];
        }
    }
}

// per-edge GATv2 score + running segment max. One warp per edge.
// lane l covers channels l (head0), 32+l (head1), 64+l (head2).
__global__ void k_score(const float* __restrict__ att, int E) {
    int w = (blockIdx.x * blockDim.x + threadIdx.x) >> 5;
    int lane = threadIdx.x & 31;
    if (w >= E) return;
    int s = g_src[w], d = g_dst[w];
    const float* hls = g_hl + s * 96;
    const float* hrd = g_hr + d * 96;
    float v0 = hls[lane] + hrd[lane];
    float v1 = hls[32 + lane] + hrd[32 + lane];
    float v2 = hls[64 + lane] + hrd[64 + lane];
    v0 = (v0 > 0.f) ? v0 : NEG * v0;
    v1 = (v1 > 0.f) ? v1 : NEG * v1;
    v2 = (v2 > 0.f) ? v2 : NEG * v2;
    float p0 = att[lane] * v0;
    float p1 = att[32 + lane] * v1;
    float p2 = att[64 + lane] * v2;
#pragma unroll
    for (int o = 16; o; o >>= 1) {
        p0 += __shfl_xor_sync(0xffffffffu, p0, o);
        p1 += __shfl_xor_sync(0xffffffffu, p1, o);
        p2 += __shfl_xor_sync(0xffffffffu, p2, o);
    }
    if (lane == 0) {
        g_p[w * 3 + 0] = p0;
        g_p[w * 3 + 1] = p1;
        g_p[w * 3 + 2] = p2;
        atomicMax(&g_m[d * 3 + 0], fenc(p0));
        atomicMax(&g_m[d * 3 + 1], fenc(p1));
        atomicMax(&g_m[d * 3 + 2], fenc(p2));
    }
}

// p = exp(score - max[dst]); denom[dst] += p
__global__ void k_expden(int E) {
    int e = blockIdx.x * blockDim.x + threadIdx.x;
    if (e >= E) return;
    int d = g_dst[e];
#pragma unroll
    for (int h = 0; h < 3; h++) {
        float mm = fdec(g_m[d * 3 + h]);
        float pv = expf(g_p[e * 3 + h] - mm);
        g_p[e * 3 + h] = pv;
        atomicAdd(&g_den[d * 3 + h], pv);
    }
}

// out[dst] += hl[src] * alpha ; alpha = p / (denom[dst] + eps). One warp per edge.
__global__ void k_agg(float* __restrict__ ext_out, int use_internal, int E) {
    int w = (blockIdx.x * blockDim.x + threadIdx.x) >> 5;
    int lane = threadIdx.x & 31;
    if (w >= E) return;
    float* out = use_internal ? g_acc : ext_out;
    int s = g_src[w], d = g_dst[w];
    float a0 = g_p[w * 3 + 0] / (g_den[d * 3 + 0] + 1e-16f);
    float a1 = g_p[w * 3 + 1] / (g_den[d * 3 + 1] + 1e-16f);
    float a2 = g_p[w * 3 + 2] / (g_den[d * 3 + 2] + 1e-16f);
    const float* hls = g_hl + s * 96;
    float* od = out + d * 96;
    atomicAdd(&od[lane],      hls[lane]      * a0);
    atomicAdd(&od[32 + lane], hls[32 + lane] * a1);
    atomicAdd(&od[64 + lane], hls[64 + lane] * a2);
}

// ---------------- launch ------------------------------------------------------

extern "C" void kernel_launch(void* const* d_in, const int* in_sizes, int n_in,
                              void* d_out, int out_size) {
    const float*     x     = (const float*)d_in[0];
    const void*      ei    = (const void*)d_in[1];
    const float*     W0    = (const float*)d_in[2];
    const float*     Wl1   = (const float*)d_in[3];
    const float*     bl1   = (const float*)d_in[4];
    const float*     Wr1   = (const float*)d_in[5];
    const float*     br1   = (const float*)d_in[6];
    const float*     att1  = (const float*)d_in[7];
    const float*     b1    = (const float*)d_in[8];
    const float*     Wf    = (const float*)d_in[9];
    const float*     bf    = (const float*)d_in[10];
    const float*     Wl2   = (const float*)d_in[11];
    const float*     bl2   = (const float*)d_in[12];
    const float*     Wr2   = (const float*)d_in[13];
    const float*     br2   = (const float*)d_in[14];
    const float*     att2  = (const float*)d_in[15];
    const float*     b2    = (const float*)d_in[16];
    const float*     Wlast = (const float*)d_in[17];
    const float*     blast = (const float*)d_in[18];
    float* out = (float*)d_out;

    int n = in_sizes[0] / 128;
    int E = in_sizes[1] / 2;

    dim3 nb(96, 4);
    int nodeGrid = (n + 15) / 16;
    int edgeWarpGrid = (E + 7) / 8;   // 8 warps (edges) per 256-thread block

    k_detect<<<1, 1>>>((const int*)ei);
    k_edges<<<(E + 255) / 256, 256>>>(ei, E);
    k_lin0<<<(n * 16 + 255) / 256, 256>>>(x, W0, n);
    k_node1<<<nodeGrid, nb>>>(Wl1, bl1, Wr1, br1, Wf, bf, b1, n);

    // ---- layer 1 edge phase ----
    k_reset<<<(3 * n + 255) / 256, 256>>>(3 * n);
    k_score<<<edgeWarpGrid, 256>>>(att1, E);
    k_expden<<<(E + 255) / 256, 256>>>(E);
    k_agg<<<edgeWarpGrid, 256>>>(out, 1, E);   // into g_acc

    // ---- layer 2 node transforms (relu fused on load), init d_out with skip ----
    k_node2<<<nodeGrid, nb>>>(Wl2, bl2, Wr2, br2, Wlast, blast, b2, out, n);

    // ---- layer 2 edge phase ----
    k_reset<<<(3 * n + 255) / 256, 256>>>(3 * n);
    k_score<<<edgeWarpGrid, 256>>>(att2, E);
    k_expden<<<(E + 255) / 256, 256>>>(E);
    k_agg<<<edgeWarpGrid, 256>>>(out, 0, E);   // into d_out
}

// round 5
// speedup vs baseline: 2.1906x; 2.1906x over previous
#include <cuda_runtime.h>

#define MAXN 100000
#define MAXE 1600000
#define NEG 0.2f

// ---------------- scratch (static device globals; no allocation) -------------
__device__ float g_h0 [MAXN * 16];    // relu(x@W0)
__device__ float g_hl [MAXN * 96];    // source transform (current layer)
__device__ float g_hr [MAXN * 96];    // target transform (current layer)
__device__ float g_acc[MAXN * 96];    // layer-1 accumulator = skip + b1 + msgs
__device__ int   g_src[MAXE];
__device__ int   g_dst[MAXE];
__device__ int   g_ssrc[MAXE];        // src ids sorted by dst (CSR payload)
__device__ int   g_cnt[MAXN];         // in-degree histogram
__device__ int   g_rs [MAXN + 1];     // CSR row starts
__device__ int   g_cur[MAXN];         // scatter cursors
__device__ int   g_bsum[128];
__device__ int   g_boff[128];
__device__ int   g_is64;

// ---------------- edge decode + histogram ------------------------------------

// Detect int64 vs int32 edge_index: node ids < 2^17, so int64 => odd words 0.
__global__ void k_detect(const int* __restrict__ p) {
    int acc = 0;
#pragma unroll
    for (int i = 1; i < 64; i += 2) acc |= p[i];
    g_is64 = (acc == 0) ? 1 : 0;
}

__global__ void k_zero_cnt(int n) {
    int i = blockIdx.x * blockDim.x + threadIdx.x;
    if (i < n) g_cnt[i] = 0;
}

__global__ void k_edges(const void* __restrict__ ei, int E) {
    int i = blockIdx.x * blockDim.x + threadIdx.x;
    if (i >= E) return;
    int s, d;
    if (g_is64) {
        const long long* p = (const long long*)ei;
        s = (int)p[i]; d = (int)p[E + i];
    } else {
        const int* p = (const int*)ei;
        s = p[i]; d = p[E + i];
    }
    g_src[i] = s;
    g_dst[i] = d;
    atomicAdd(&g_cnt[d], 1);
}

// ---------------- scan (3-kernel exclusive prefix sum over g_cnt) ------------

__global__ void k_scan1(int n) {
    __shared__ int tmp[1024];
    int tid = threadIdx.x;
    int i = blockIdx.x * 1024 + tid;
    int v = (i < n) ? g_cnt[i] : 0;
    tmp[tid] = v;
    __syncthreads();
#pragma unroll
    for (int o = 1; o < 1024; o <<= 1) {
        int t = (tid >= o) ? tmp[tid - o] : 0;
        __syncthreads();
        tmp[tid] += t;
        __syncthreads();
    }
    if (i < n) g_rs[i] = tmp[tid] - v;         // block-local exclusive
    if (tid == 1023) g_bsum[blockIdx.x] = tmp[tid];
}

__global__ void k_scan2(int nb) {
    __shared__ int tmp[128];
    int tid = threadIdx.x;
    int v = (tid < nb) ? g_bsum[tid] : 0;
    tmp[tid] = v;
    __syncthreads();
#pragma unroll
    for (int o = 1; o < 128; o <<= 1) {
        int t = (tid >= o) ? tmp[tid - o] : 0;
        __syncthreads();
        tmp[tid] += t;
        __syncthreads();
    }
    if (tid < nb) g_boff[tid] = tmp[tid] - v;  // exclusive block offsets
}

__global__ void k_scan3(int n, int E) {
    int i = blockIdx.x * blockDim.x + threadIdx.x;
    if (i < n) {
        int r = g_rs[i] + g_boff[i >> 10];
        g_rs[i] = r;
        g_cur[i] = r;
    }
    if (i == 0) g_rs[n] = E;
}

__global__ void k_scatter(int E) {
    int i = blockIdx.x * blockDim.x + threadIdx.x;
    if (i >= E) return;
    int d = g_dst[i];
    int pos = atomicAdd(&g_cur[d], 1);
    g_ssrc[pos] = g_src[i];
}

// ---------------- node transforms --------------------------------------------

// h0 = relu(x @ W0) : [n,128]@[128,16]
__global__ void k_lin0(const float* __restrict__ x, const float* __restrict__ W0, int n) {
    int t = blockIdx.x * blockDim.x + threadIdx.x;
    if (t >= n * 16) return;
    int row = t >> 4, c = t & 15;
    const float* xr = x + row * 128;
    float acc = 0.f;
#pragma unroll 8
    for (int k = 0; k < 128; k++) acc = fmaf(xr[k], W0[k * 16 + c], acc);
    g_h0[t] = fmaxf(acc, 0.f);
}

// layer-1 transforms: weights in registers (one output column per thread),
// h rows staged in shared (broadcast reads). 64 rows per block.
__global__ void __launch_bounds__(384)
k_node1(const float* __restrict__ Wl, const float* __restrict__ bl,
        const float* __restrict__ Wr, const float* __restrict__ br,
        const float* __restrict__ Wf, const float* __restrict__ bf,
        const float* __restrict__ b1, int n) {
    __shared__ float sh[64 * 16];
    int c = threadIdx.x, ty = threadIdx.y;
    int tid = ty * 96 + c;
    int row0 = blockIdx.x * 64;
    float wl[16], wr[16], wf[16];
#pragma unroll
    for (int k = 0; k < 16; k++) {
        wl[k] = Wl[k * 96 + c];
        wr[k] = Wr[k * 96 + c];
        wf[k] = Wf[k * 96 + c];
    }
    float cbl = bl[c], cbr = br[c], cbf = bf[c] + b1[c];
    for (int i = tid; i < 1024; i += 384) {
        int r = i >> 4, k = i & 15;
        int row = row0 + r;
        sh[i] = (row < n) ? g_h0[row * 16 + k] : 0.f;
    }
    __syncthreads();
    for (int r = ty; r < 64; r += 4) {
        int row = row0 + r;
        if (row >= n) continue;
        float a0 = cbl, a1 = cbr, a2 = cbf;
#pragma unroll
        for (int k = 0; k < 16; k++) {
            float h = sh[r * 16 + k];
            a0 = fmaf(h, wl[k], a0);
            a1 = fmaf(h, wr[k], a1);
            a2 = fmaf(h, wf[k], a2);
        }
        g_hl[row * 96 + c] = a0;
        g_hr[row * 96 + c] = a1;
        g_acc[row * 96 + c] = a2;
    }
}

// layer-2 transforms from pre-relu accumulator; K=96 in 6 chunks of 16.
// Weights for the chunk in registers; 32 rows/block, 8 rows/thread.
__global__ void __launch_bounds__(384, 1)
k_node2(const float* __restrict__ Wl, const float* __restrict__ bl,
        const float* __restrict__ Wr, const float* __restrict__ br,
        const float* __restrict__ Wo, const float* __restrict__ bo,
        const float* __restrict__ b2, float* __restrict__ out, int n) {
    __shared__ float sh[32 * 16];
    int c = threadIdx.x, ty = threadIdx.y;
    int tid = ty * 96 + c;
    int row0 = blockIdx.x * 32;
    float a0[8], a1[8], a2[8];
    float ibl = bl[c], ibr = br[c], ibo = bo[c] + b2[c];
#pragma unroll
    for (int j = 0; j < 8; j++) { a0[j] = ibl; a1[j] = ibr; a2[j] = ibo; }
    for (int kt = 0; kt < 6; kt++) {
        float wl[16], wr[16], wo[16];
#pragma unroll
        for (int k = 0; k < 16; k++) {
            wl[k] = Wl[(kt * 16 + k) * 96 + c];
            wr[k] = Wr[(kt * 16 + k) * 96 + c];
            wo[k] = Wo[(kt * 16 + k) * 96 + c];
        }
        for (int i = tid; i < 512; i += 384) {
            int r = i >> 4, k = i & 15;
            int row = row0 + r;
            float v = (row < n) ? g_acc[row * 96 + kt * 16 + k] : 0.f;
            sh[i] = fmaxf(v, 0.f);   // relu(h1)
        }
        __syncthreads();
#pragma unroll
        for (int j = 0; j < 8; j++) {
            int r = ty + 4 * j;
#pragma unroll
            for (int k = 0; k < 16; k++) {
                float h = sh[r * 16 + k];
                a0[j] = fmaf(h, wl[k], a0[j]);
                a1[j] = fmaf(h, wr[k], a1[j]);
                a2[j] = fmaf(h, wo[k], a2[j]);
            }
        }
        __syncthreads();
    }
#pragma unroll
    for (int j = 0; j < 8; j++) {
        int row = row0 + ty + 4 * j;
        if (row < n) {
            g_hl[row * 96 + c] = a0[j];
            g_hr[row * 96 + c] = a1[j];
            out[row * 96 + c] = a2[j];
        }
    }
}

// ---------------- fused GATv2 edge phase (warp per destination node) ---------
// lane l covers channels l (head0), 32+l (head1), 64+l (head2).
// out[v] += sum_e p_e*hl[src_e] / (sum_e p_e + eps), p_e = exp(att . leaky(hl+hr))
// NOTE: internal target (g_acc) must be resolved in DEVICE code — passing the
// __device__ symbol from host is the bug that sank round 3.
__global__ void k_gat(const float* __restrict__ att, float* __restrict__ ext_out,
                      int use_internal, int n) {
    int v = (blockIdx.x * blockDim.x + threadIdx.x) >> 5;
    int lane = threadIdx.x & 31;
    if (v >= n) return;
    float* out = use_internal ? g_acc : ext_out;
    int beg = g_rs[v], end = g_rs[v + 1];
    float at0 = att[lane], at1 = att[32 + lane], at2 = att[64 + lane];
    const float* hr = g_hr + (size_t)v * 96;
    float hr0 = hr[lane], hr1 = hr[32 + lane], hr2 = hr[64 + lane];
    float den0 = 0.f, den1 = 0.f, den2 = 0.f;
    float ac0 = 0.f, ac1 = 0.f, ac2 = 0.f;
#pragma unroll 2
    for (int e = beg; e < end; e++) {
        int s = g_ssrc[e];
        const float* hl = g_hl + (size_t)s * 96;
        float h0 = hl[lane], h1 = hl[32 + lane], h2 = hl[64 + lane];
        float v0 = h0 + hr0, v1 = h1 + hr1, v2 = h2 + hr2;
        v0 = (v0 > 0.f) ? v0 : NEG * v0;
        v1 = (v1 > 0.f) ? v1 : NEG * v1;
        v2 = (v2 > 0.f) ? v2 : NEG * v2;
        float s0 = at0 * v0, s1 = at1 * v1, s2 = at2 * v2;
#pragma unroll
        for (int o = 16; o; o >>= 1) {
            s0 += __shfl_xor_sync(0xffffffffu, s0, o);
            s1 += __shfl_xor_sync(0xffffffffu, s1, o);
            s2 += __shfl_xor_sync(0xffffffffu, s2, o);
        }
        float p0 = __expf(s0), p1 = __expf(s1), p2 = __expf(s2);
        den0 += p0; den1 += p1; den2 += p2;
        ac0 = fmaf(p0, h0, ac0);
        ac1 = fmaf(p1, h1, ac1);
        ac2 = fmaf(p2, h2, ac2);
    }
    float* o = out + (size_t)v * 96;
    o[lane]      += ac0 / (den0 + 1e-16f);
    o[32 + lane] += ac1 / (den1 + 1e-16f);
    o[64 + lane] += ac2 / (den2 + 1e-16f);
}

// ---------------- launch ------------------------------------------------------

extern "C" void kernel_launch(void* const* d_in, const int* in_sizes, int n_in,
                              void* d_out, int out_size) {
    const float* x     = (const float*)d_in[0];
    const void*  ei    = (const void*)d_in[1];
    const float* W0    = (const float*)d_in[2];
    const float* Wl1   = (const float*)d_in[3];
    const float* bl1   = (const float*)d_in[4];
    const float* Wr1   = (const float*)d_in[5];
    const float* br1   = (const float*)d_in[6];
    const float* att1  = (const float*)d_in[7];
    const float* b1    = (const float*)d_in[8];
    const float* Wf    = (const float*)d_in[9];
    const float* bf    = (const float*)d_in[10];
    const float* Wl2   = (const float*)d_in[11];
    const float* bl2   = (const float*)d_in[12];
    const float* Wr2   = (const float*)d_in[13];
    const float* br2   = (const float*)d_in[14];
    const float* att2  = (const float*)d_in[15];
    const float* b2    = (const float*)d_in[16];
    const float* Wlast = (const float*)d_in[17];
    const float* blast = (const float*)d_in[18];
    float* out = (float*)d_out;

    int n = in_sizes[0] / 128;
    int E = in_sizes[1] / 2;
    int NB = (n + 1023) / 1024;          // scan blocks (<=128)

    // ---- CSR build (by destination) ----
    k_detect<<<1, 1>>>((const int*)ei);
    k_zero_cnt<<<(n + 255) / 256, 256>>>(n);
    k_edges<<<(E + 255) / 256, 256>>>(ei, E);
    k_scan1<<<NB, 1024>>>(n);
    k_scan2<<<1, 128>>>(NB);
    k_scan3<<<(n + 255) / 256, 256>>>(n, E);
    k_scatter<<<(E + 255) / 256, 256>>>(E);

    // ---- node transforms ----
    k_lin0<<<(n * 16 + 255) / 256, 256>>>(x, W0, n);
    k_node1<<<(n + 63) / 64, dim3(96, 4)>>>(Wl1, bl1, Wr1, br1, Wf, bf, b1, n);

    // ---- layer 1 edge phase (into g_acc which holds skip + b1) ----
    k_gat<<<(n + 7) / 8, 256>>>(att1, out, 1, n);

    // ---- layer 2 node transforms (relu fused on load; out gets skip + b2) ----
    k_node2<<<(n + 31) / 32, dim3(96, 4)>>>(Wl2, bl2, Wr2, br2, Wlast, blast, b2, out, n);

    // ---- layer 2 edge phase (into d_out) ----
    k_gat<<<(n + 7) / 8, 256>>>(att2, out, 0, n);
}

// round 6
// speedup vs baseline: 2.2248x; 1.0156x over previous
#include <cuda_runtime.h>

#define MAXN 100000
#define MAXE 1600000
#define NEG 0.2f

typedef unsigned long long ull;

// ---------------- scratch (static device globals; no allocation) -------------
__device__ float g_h0 [MAXN * 16];    // relu(x@W0)
__device__ float g_hl [MAXN * 96];    // source transform (current layer)
__device__ float g_hr [MAXN * 96];    // target transform (current layer)
__device__ float g_acc[MAXN * 96];    // layer-1 accumulator = skip + b1 + msgs
__device__ int   g_src[MAXE];
__device__ int   g_dst[MAXE];
__device__ int   g_ssrc[MAXE];        // src ids sorted by dst (CSR payload)
__device__ int   g_cnt[MAXN];         // in-degree histogram
__device__ int   g_rs [MAXN + 1];     // CSR row starts
__device__ int   g_cur[MAXN];         // scatter cursors
__device__ int   g_bsum[128];
__device__ int   g_boff[128];
__device__ int   g_is64;

// ---------------- f32x2 helpers (FFMA2 only reachable via PTX) ---------------
__device__ __forceinline__ void ffma2(ull& acc, ull a, ull b) {
    asm("fma.rn.f32x2 %0, %1, %2, %0;" : "+l"(acc) : "l"(a), "l"(b));
}
__device__ __forceinline__ ull pack2(float x, float y) {
    ull r; asm("mov.b64 %0, {%1, %2};" : "=l"(r) : "f"(x), "f"(y)); return r;
}
__device__ __forceinline__ float2 unpack2(ull v) {
    float2 r; asm("mov.b64 {%0, %1}, %2;" : "=f"(r.x), "=f"(r.y) : "l"(v)); return r;
}

// ---------------- edge decode + histogram ------------------------------------

// Detect int64 vs int32 edge_index: node ids < 2^17, so int64 => odd words 0.
__global__ void k_detect(const int* __restrict__ p) {
    int acc = 0;
#pragma unroll
    for (int i = 1; i < 64; i += 2) acc |= p[i];
    g_is64 = (acc == 0) ? 1 : 0;
}

__global__ void k_zero_cnt(int n) {
    int i = blockIdx.x * blockDim.x + threadIdx.x;
    if (i < n) g_cnt[i] = 0;
}

__global__ void k_edges(const void* __restrict__ ei, int E) {
    int i = blockIdx.x * blockDim.x + threadIdx.x;
    if (i >= E) return;
    int s, d;
    if (g_is64) {
        const long long* p = (const long long*)ei;
        s = (int)p[i]; d = (int)p[E + i];
    } else {
        const int* p = (const int*)ei;
        s = p[i]; d = p[E + i];
    }
    g_src[i] = s;
    g_dst[i] = d;
    atomicAdd(&g_cnt[d], 1);
}

// ---------------- scan (3-kernel exclusive prefix sum over g_cnt) ------------

__global__ void k_scan1(int n) {
    __shared__ int tmp[1024];
    int tid = threadIdx.x;
    int i = blockIdx.x * 1024 + tid;
    int v = (i < n) ? g_cnt[i] : 0;
    tmp[tid] = v;
    __syncthreads();
#pragma unroll
    for (int o = 1; o < 1024; o <<= 1) {
        int t = (tid >= o) ? tmp[tid - o] : 0;
        __syncthreads();
        tmp[tid] += t;
        __syncthreads();
    }
    if (i < n) g_rs[i] = tmp[tid] - v;         // block-local exclusive
    if (tid == 1023) g_bsum[blockIdx.x] = tmp[tid];
}

__global__ void k_scan2(int nb) {
    __shared__ int tmp[128];
    int tid = threadIdx.x;
    int v = (tid < nb) ? g_bsum[tid] : 0;
    tmp[tid] = v;
    __syncthreads();
#pragma unroll
    for (int o = 1; o < 128; o <<= 1) {
        int t = (tid >= o) ? tmp[tid - o] : 0;
        __syncthreads();
        tmp[tid] += t;
        __syncthreads();
    }
    if (tid < nb) g_boff[tid] = tmp[tid] - v;  // exclusive block offsets
}

__global__ void k_scan3(int n, int E) {
    int i = blockIdx.x * blockDim.x + threadIdx.x;
    if (i < n) {
        int r = g_rs[i] + g_boff[i >> 10];
        g_rs[i] = r;
        g_cur[i] = r;
    }
    if (i == 0) g_rs[n] = E;
}

__global__ void k_scatter(int E) {
    int i = blockIdx.x * blockDim.x + threadIdx.x;
    if (i >= E) return;
    int d = g_dst[i];
    int pos = atomicAdd(&g_cur[d], 1);
    g_ssrc[pos] = g_src[i];
}

// ---------------- node transforms --------------------------------------------

// h0 = relu(x @ W0) : [n,128]@[128,16]. Shared-staged, float4 global loads.
__global__ void __launch_bounds__(256)
k_lin0(const float* __restrict__ x, const float* __restrict__ W0, int n) {
    __shared__ float sx[16 * 128];   // 16 rows of x
    __shared__ float sw[128 * 16];   // W0
    int tid = threadIdx.x;
    int row0 = blockIdx.x * 16;
    for (int i = tid; i < 512; i += 256)
        ((float4*)sw)[i] = ((const float4*)W0)[i];
    for (int i = tid; i < 512; i += 256) {
        int r = i >> 5;                // row within tile
        int row = row0 + r;
        float4 v = make_float4(0.f, 0.f, 0.f, 0.f);
        if (row < n) v = ((const float4*)x)[row * 32 + (i & 31)];
        ((float4*)sx)[i] = v;
    }
    __syncthreads();
    int r = tid >> 4, c = tid & 15;
    const float4* sxr = (const float4*)(sx + r * 128);
    float acc = 0.f;
#pragma unroll
    for (int k4 = 0; k4 < 32; k4++) {
        float4 h = sxr[k4];
        acc = fmaf(h.x, sw[(4 * k4 + 0) * 16 + c], acc);
        acc = fmaf(h.y, sw[(4 * k4 + 1) * 16 + c], acc);
        acc = fmaf(h.z, sw[(4 * k4 + 2) * 16 + c], acc);
        acc = fmaf(h.w, sw[(4 * k4 + 3) * 16 + c], acc);
    }
    int row = row0 + r;
    if (row < n) g_h0[row * 16 + c] = fmaxf(acc, 0.f);
}

// layer-1 transforms: weights in registers (one output column per thread),
// h rows staged in shared (broadcast reads). 64 rows per block.
__global__ void __launch_bounds__(384)
k_node1(const float* __restrict__ Wl, const float* __restrict__ bl,
        const float* __restrict__ Wr, const float* __restrict__ br,
        const float* __restrict__ Wf, const float* __restrict__ bf,
        const float* __restrict__ b1, int n) {
    __shared__ float sh[64 * 16];
    int c = threadIdx.x, ty = threadIdx.y;
    int tid = ty * 96 + c;
    int row0 = blockIdx.x * 64;
    float wl[16], wr[16], wf[16];
#pragma unroll
    for (int k = 0; k < 16; k++) {
        wl[k] = Wl[k * 96 + c];
        wr[k] = Wr[k * 96 + c];
        wf[k] = Wf[k * 96 + c];
    }
    float cbl = bl[c], cbr = br[c], cbf = bf[c] + b1[c];
    for (int i = tid; i < 1024; i += 384) {
        int r = i >> 4, k = i & 15;
        int row = row0 + r;
        sh[i] = (row < n) ? g_h0[row * 16 + k] : 0.f;
    }
    __syncthreads();
    for (int r = ty; r < 64; r += 4) {
        int row = row0 + r;
        if (row >= n) continue;
        float a0 = cbl, a1 = cbr, a2 = cbf;
#pragma unroll
        for (int k = 0; k < 16; k++) {
            float h = sh[r * 16 + k];
            a0 = fmaf(h, wl[k], a0);
            a1 = fmaf(h, wr[k], a1);
            a2 = fmaf(h, wf[k], a2);
        }
        g_hl[row * 96 + c] = a0;
        g_hr[row * 96 + c] = a1;
        g_acc[row * 96 + c] = a2;
    }
}

// layer-2 transforms via packed f32x2 FMA (FFMA2): rows processed in pairs.
// sh is transposed [k][r] with stride 34 (even => aligned LDS.64; bank
// (2k+r)%32 => conflict-free). 32 rows/block; thread handles 4 row-pairs.
__global__ void __launch_bounds__(384, 1)
k_node2(const float* __restrict__ Wl, const float* __restrict__ bl,
        const float* __restrict__ Wr, const float* __restrict__ br,
        const float* __restrict__ Wo, const float* __restrict__ bo,
        const float* __restrict__ b2, float* __restrict__ out, int n) {
    __shared__ float sh[16 * 34];
    int c = threadIdx.x, ty = threadIdx.y;
    int tid = ty * 96 + c;
    int row0 = blockIdx.x * 32;
    ull a0[4], a1[4], a2[4];
    float ibl = bl[c], ibr = br[c], ibo = bo[c] + b2[c];
#pragma unroll
    for (int jp = 0; jp < 4; jp++) {
        a0[jp] = pack2(ibl, ibl);
        a1[jp] = pack2(ibr, ibr);
        a2[jp] = pack2(ibo, ibo);
    }
    for (int kt = 0; kt < 6; kt++) {
        float wl[16], wr[16], wo[16];
#pragma unroll
        for (int k = 0; k < 16; k++) {
            wl[k] = Wl[(kt * 16 + k) * 96 + c];
            wr[k] = Wr[(kt * 16 + k) * 96 + c];
            wo[k] = Wo[(kt * 16 + k) * 96 + c];
        }
        for (int i = tid; i < 512; i += 384) {
            int k = i & 15, r = i >> 4;
            int row = row0 + r;
            float v = (row < n) ? g_acc[row * 96 + kt * 16 + k] : 0.f;
            sh[k * 34 + r] = fmaxf(v, 0.f);   // relu(h1), transposed
        }
        __syncthreads();
#pragma unroll
        for (int k = 0; k < 16; k++) {
            ull wl2 = pack2(wl[k], wl[k]);
            ull wr2 = pack2(wr[k], wr[k]);
            ull wo2 = pack2(wo[k], wo[k]);
#pragma unroll
            for (int jp = 0; jp < 4; jp++) {
                int p = ty + 4 * jp;
                ull h2 = *(const ull*)&sh[k * 34 + 2 * p];
                ffma2(a0[jp], h2, wl2);
                ffma2(a1[jp], h2, wr2);
                ffma2(a2[jp], h2, wo2);
            }
        }
        __syncthreads();
    }
#pragma unroll
    for (int jp = 0; jp < 4; jp++) {
        int p = ty + 4 * jp;
        float2 v0 = unpack2(a0[jp]);
        float2 v1 = unpack2(a1[jp]);
        float2 v2 = unpack2(a2[jp]);
        int ra = row0 + 2 * p, rb = ra + 1;
        if (ra < n) {
            g_hl[ra * 96 + c] = v0.x; g_hr[ra * 96 + c] = v1.x; out[ra * 96 + c] = v2.x;
        }
        if (rb < n) {
            g_hl[rb * 96 + c] = v0.y; g_hr[rb * 96 + c] = v1.y; out[rb * 96 + c] = v2.y;
        }
    }
}

// ---------------- fused GATv2 edge phase (warp per destination node) ---------
// lane l covers channels l (head0), 32+l (head1), 64+l (head2).
// CSR indices fetched 32-at-a-time by lanes, extracted via shfl so the gather
// loads for edge j+1 can issue during edge j's reduction.
// NOTE: internal target (g_acc) resolved in DEVICE code (host symbol != dev ptr).
__global__ void k_gat(const float* __restrict__ att, float* __restrict__ ext_out,
                      int use_internal, int n) {
    int v = (blockIdx.x * blockDim.x + threadIdx.x) >> 5;
    int lane = threadIdx.x & 31;
    if (v >= n) return;
    float* out = use_internal ? g_acc : ext_out;
    int beg = g_rs[v], end = g_rs[v + 1];
    float at0 = att[lane], at1 = att[32 + lane], at2 = att[64 + lane];
    const float* hr = g_hr + (size_t)v * 96;
    float hr0 = hr[lane], hr1 = hr[32 + lane], hr2 = hr[64 + lane];
    float den0 = 0.f, den1 = 0.f, den2 = 0.f;
    float ac0 = 0.f, ac1 = 0.f, ac2 = 0.f;
    for (int base = beg; base < end; base += 32) {
        int m = end - base; if (m > 32) m = 32;
        int myi = (lane < m) ? g_ssrc[base + lane] : 0;
#pragma unroll 4
        for (int j = 0; j < m; j++) {
            int s = __shfl_sync(0xffffffffu, myi, j);
            const float* hl = g_hl + (size_t)s * 96;
            float h0 = hl[lane], h1 = hl[32 + lane], h2 = hl[64 + lane];
            float v0 = h0 + hr0, v1 = h1 + hr1, v2 = h2 + hr2;
            v0 = (v0 > 0.f) ? v0 : NEG * v0;
            v1 = (v1 > 0.f) ? v1 : NEG * v1;
            v2 = (v2 > 0.f) ? v2 : NEG * v2;
            float s0 = at0 * v0, s1 = at1 * v1, s2 = at2 * v2;
#pragma unroll
            for (int o = 16; o; o >>= 1) {
                s0 += __shfl_xor_sync(0xffffffffu, s0, o);
                s1 += __shfl_xor_sync(0xffffffffu, s1, o);
                s2 += __shfl_xor_sync(0xffffffffu, s2, o);
            }
            float p0 = __expf(s0), p1 = __expf(s1), p2 = __expf(s2);
            den0 += p0; den1 += p1; den2 += p2;
            ac0 = fmaf(p0, h0, ac0);
            ac1 = fmaf(p1, h1, ac1);
            ac2 = fmaf(p2, h2, ac2);
        }
    }
    float* o = out + (size_t)v * 96;
    o[lane]      += ac0 / (den0 + 1e-16f);
    o[32 + lane] += ac1 / (den1 + 1e-16f);
    o[64 + lane] += ac2 / (den2 + 1e-16f);
}

// ---------------- launch ------------------------------------------------------

extern "C" void kernel_launch(void* const* d_in, const int* in_sizes, int n_in,
                              void* d_out, int out_size) {
    const float* x     = (const float*)d_in[0];
    const void*  ei    = (const void*)d_in[1];
    const float* W0    = (const float*)d_in[2];
    const float* Wl1   = (const float*)d_in[3];
    const float* bl1   = (const float*)d_in[4];
    const float* Wr1   = (const float*)d_in[5];
    const float* br1   = (const float*)d_in[6];
    const float* att1  = (const float*)d_in[7];
    const float* b1    = (const float*)d_in[8];
    const float* Wf    = (const float*)d_in[9];
    const float* bf    = (const float*)d_in[10];
    const float* Wl2   = (const float*)d_in[11];
    const float* bl2   = (const float*)d_in[12];
    const float* Wr2   = (const float*)d_in[13];
    const float* br2   = (const float*)d_in[14];
    const float* att2  = (const float*)d_in[15];
    const float* b2    = (const float*)d_in[16];
    const float* Wlast = (const float*)d_in[17];
    const float* blast = (const float*)d_in[18];
    float* out = (float*)d_out;

    int n = in_sizes[0] / 128;
    int E = in_sizes[1] / 2;
    int NB = (n + 1023) / 1024;          // scan blocks (<=128)

    // ---- CSR build (by destination) ----
    k_detect<<<1, 1>>>((const int*)ei);
    k_zero_cnt<<<(n + 255) / 256, 256>>>(n);
    k_edges<<<(E + 255) / 256, 256>>>(ei, E);
    k_scan1<<<NB, 1024>>>(n);
    k_scan2<<<1, 128>>>(NB);
    k_scan3<<<(n + 255) / 256, 256>>>(n, E);
    k_scatter<<<(E + 255) / 256, 256>>>(E);

    // ---- node transforms ----
    k_lin0<<<(n + 15) / 16, 256>>>(x, W0, n);
    k_node1<<<(n + 63) / 64, dim3(96, 4)>>>(Wl1, bl1, Wr1, br1, Wf, bf, b1, n);

    // ---- layer 1 edge phase (into g_acc which holds skip + b1) ----
    k_gat<<<(n + 7) / 8, 256>>>(att1, out, 1, n);

    // ---- layer 2 node transforms (relu fused on load; out gets skip + b2) ----
    k_node2<<<(n + 31) / 32, dim3(96, 4)>>>(Wl2, bl2, Wr2, br2, Wlast, blast, b2, out, n);

    // ---- layer 2 edge phase (into d_out) ----
    k_gat<<<(n + 7) / 8, 256>>>(att2, out, 0, n);
}